// round 6
// baseline (speedup 1.0000x reference)
#include <cuda_runtime.h>
#include <cuda_bf16.h>
#include <cstdint>
#include <math.h>

// ---------------------------------------------------------------------------
// AtomicRouteConv — restructured GNN pipeline.
// GEMMs on HMMA (mma.sync m16n8k16 bf16) with split-bf16 fp32 emulation:
//   A = Ah + Al, B = Bh + Bl;  D = Ah*Bh + Ah*Bl + Al*Bh  (err ~1.5e-5)
// R6: weights in global bf16 hi/lo (L1-resident) instead of smem ->
//     smem holds only the A tile -> 2 CTAs/SM instead of 1 (occ 12.4% -> 25%).
// ---------------------------------------------------------------------------

#define C      128
#define NM     50000
#define ND     50000
#define NE1    640000
#define NE2    640000
#define INV_SQRT_C 0.08838834764831843f

// padded smem row: 128 bf16 = 64 words, pad to 68 words (conflict-free frags)
#define RP 68
#define RP8 (8*RP)
#define AREA (128*RP)            // words per hi or lo region (34816 B)
#define WMAT 8192                // words per weight matrix (128 rows x 64 words)

// ---------------- scratch ----------------------------------------------------
__device__ __align__(16) float g_smid[NM * C];
__device__ __align__(16) float g_deg [NM + 48];
__device__ __align__(16) float g_h   [NM * C];
__device__ __align__(16) float g_K   [NM * C];
__device__ __align__(16) float g_V   [NM * C];
__device__ __align__(16) float g_Q   [ND * C];
__device__ __align__(16) float g_esc [NE2];
__device__ __align__(16) uint32_t g_wh[5 * WMAT];   // W1,W2,k,v,q  (bf16x2 hi)
__device__ __align__(16) uint32_t g_wl[5 * WMAT];   //              (bf16x2 lo)
__device__ float g_sum[1];
__device__ int   g_idx64;

// ---------------- helpers ---------------------------------------------------
__device__ __forceinline__ int ld_idx(const void* ei, long long pos, int is64) {
    if (is64) return (int)(((const long long*)ei)[pos]);
    return ((const int*)ei)[pos];
}
__device__ __forceinline__ void red_add_v4(float* p, float4 v) {
    asm volatile("red.global.add.v4.f32 [%0], {%1,%2,%3,%4};"
                 :: "l"(p), "f"(v.x), "f"(v.y), "f"(v.z), "f"(v.w) : "memory");
}
// split two fp32 into packed bf16x2 hi + lo (lo-half = f0, hi-half = f1)
__device__ __forceinline__ void split2(float f0, float f1, uint32_t& h, uint32_t& l) {
    uint32_t hp;
    asm("cvt.rn.bf16x2.f32 %0, %1, %2;" : "=r"(hp) : "f"(f1), "f"(f0));
    float f0h = __uint_as_float(hp << 16);
    float f1h = __uint_as_float(hp & 0xffff0000u);
    float r0 = f0 - f0h, r1 = f1 - f1h;
    asm("cvt.rn.bf16x2.f32 %0, %1, %2;" : "=r"(l) : "f"(r1), "f"(r0));
    h = hp;
}
__device__ __forceinline__ void mma_bf16(float* c, const uint32_t* a,
                                         uint32_t b0, uint32_t b1) {
    asm volatile("mma.sync.aligned.m16n8k16.row.col.f32.bf16.bf16.f32 "
        "{%0,%1,%2,%3}, {%4,%5,%6,%7}, {%8,%9}, {%0,%1,%2,%3};"
        : "+f"(c[0]), "+f"(c[1]), "+f"(c[2]), "+f"(c[3])
        : "r"(a[0]), "r"(a[1]), "r"(a[2]), "r"(a[3]), "r"(b0), "r"(b1));
}

// convert a 128x128 fp32 tile (guarded rows) into hi/lo bf16 smem regions,
// optional per-row scale. 256 threads: thread t -> row t>>1, col half (t&1)*64.
__device__ __forceinline__ void convert_tile(const float* __restrict__ A, int m0, int M,
                                             uint32_t* __restrict__ Dh,
                                             uint32_t* __restrict__ Dl,
                                             const float* __restrict__ rowscale) {
    const int t = threadIdx.x;
    const int r = t >> 1, c0 = (t & 1) * 64;
    const int row = m0 + r;
    const bool v = row < M;
    const float s = (rowscale && v) ? rowscale[row] : 1.0f;
    const float4* Ar = (const float4*)(A + (size_t)row * C + c0);
    const int wb = r * RP + (c0 >> 1);
    #pragma unroll
    for (int i = 0; i < 16; i++) {
        float4 x = v ? Ar[i] : make_float4(0.f, 0.f, 0.f, 0.f);
        uint32_t h0, l0, h1, l1;
        split2(s * x.x, s * x.y, h0, l0);
        split2(s * x.z, s * x.w, h1, l1);
        Dh[wb + i*2]   = h0; Dh[wb + i*2+1] = h1;
        Dl[wb + i*2]   = l0; Dl[wb + i*2+1] = l1;
    }
}

// warp-tile compute: acc[16][4] += A(128x128 smem) @ W^T (global bf16 hi/lo)
__device__ __forceinline__ void tile_compute(const uint32_t* __restrict__ Ah,
                                             const uint32_t* __restrict__ Al,
                                             const uint32_t* __restrict__ Wh,
                                             const uint32_t* __restrict__ Wl,
                                             float* __restrict__ acc,
                                             int w, int g, int tig) {
    #pragma unroll 1
    for (int ks = 0; ks < 8; ks++) {
        uint32_t ah[4], al[4];
        const int ab = (w * 16 + g) * RP + ks * 8 + tig;
        ah[0] = Ah[ab];     ah[1] = Ah[ab + RP8];
        ah[2] = Ah[ab + 4]; ah[3] = Ah[ab + RP8 + 4];
        al[0] = Al[ab];     al[1] = Al[ab + RP8];
        al[2] = Al[ab + 4]; al[3] = Al[ab + RP8 + 4];
        #pragma unroll
        for (int nt = 0; nt < 16; nt++) {
            const int nb = (nt * 8 + g) * 64 + ks * 8 + tig;
            uint32_t bh0 = Wh[nb], bh1 = Wh[nb + 4];
            uint32_t bl0 = Wl[nb], bl1 = Wl[nb + 4];
            float* cc = acc + nt * 4;
            mma_bf16(cc, ah, bh0, bh1);
            mma_bf16(cc, ah, bl0, bl1);
            mma_bf16(cc, al, bh0, bh1);
        }
    }
}

__device__ __forceinline__ void epilogue_write(const float* __restrict__ acc,
                                               const float* __restrict__ bsh,
                                               float* __restrict__ out,
                                               int m0, int M, int w, int g, int tig) {
    const int r0 = m0 + w * 16 + g;
    const int r1 = r0 + 8;
    #pragma unroll
    for (int nt = 0; nt < 16; nt++) {
        const int c = nt * 8 + tig * 2;
        const float b0 = bsh[c], b1 = bsh[c + 1];
        if (r0 < M) {
            float2 o = { acc[nt*4+0] + b0, acc[nt*4+1] + b1 };
            *(float2*)(out + (size_t)r0 * C + c) = o;
        }
        if (r1 < M) {
            float2 o = { acc[nt*4+2] + b0, acc[nt*4+3] + b1 };
            *(float2*)(out + (size_t)r1 * C + c) = o;
        }
    }
}

#define SMA_BYTES (2 * AREA * 4 + 1024)

// ---------------- weight prep: fp32 -> global bf16 hi/lo --------------------
__global__ void __launch_bounds__(256) prep_w_kernel(
    const float* __restrict__ W1, const float* __restrict__ W2,
    const float* __restrict__ kw, const float* __restrict__ vw,
    const float* __restrict__ qw) {
    const float* Ws[5] = {W1, W2, kw, vw, qw};
    const float* W = Ws[blockIdx.y];
    uint32_t* wh = g_wh + blockIdx.y * WMAT;
    uint32_t* wl = g_wl + blockIdx.y * WMAT;
    for (int wdx = blockIdx.x * blockDim.x + threadIdx.x; wdx < WMAT;
         wdx += gridDim.x * blockDim.x) {
        const int n = wdx >> 6, k2 = wdx & 63;
        float f0 = W[n * C + k2 * 2], f1 = W[n * C + k2 * 2 + 1];
        uint32_t h, l;
        split2(f0, f1, h, l);
        wh[wdx] = h; wl[wdx] = l;
    }
}

// ---------------- generic GEMM: out[M,128] = A[M,128] @ W^T + b -------------
__global__ void __launch_bounds__(256, 2) gemm_mma_kernel(
    const float* __restrict__ A,
    const uint32_t* __restrict__ Wh, const uint32_t* __restrict__ Wl,
    const float* __restrict__ bias, float* __restrict__ out, int M)
{
    extern __shared__ uint32_t sm[];
    uint32_t* Ah = sm;
    uint32_t* Al = sm + AREA;
    float* bsh = (float*)(sm + 2 * AREA);

    const int t = threadIdx.x;
    if (t < 128) bsh[t] = bias[t];

    const int w = t >> 5, lane = t & 31, g = lane >> 2, tig = lane & 3;
    const int ntiles = (M + 127) >> 7;

    for (int tile = blockIdx.x; tile < ntiles; tile += gridDim.x) {
        const int m0 = tile << 7;
        __syncthreads();
        convert_tile(A, m0, M, Ah, Al, (const float*)0);
        __syncthreads();

        float acc[64];
        #pragma unroll
        for (int i = 0; i < 64; i++) acc[i] = 0.0f;
        tile_compute(Ah, Al, Wh, Wl, acc, w, g, tig);
        epilogue_write(acc, bsh, out, m0, M, w, g, tig);
    }
}

// ---------------- fused K+V GEMM --------------------------------------------
__global__ void __launch_bounds__(256, 2) gemm_kv_kernel(
    const float* __restrict__ A,
    const uint32_t* __restrict__ Wkh, const uint32_t* __restrict__ Wkl,
    const float* __restrict__ bk, float* __restrict__ outK,
    const uint32_t* __restrict__ Wvh, const uint32_t* __restrict__ Wvl,
    const float* __restrict__ bv, float* __restrict__ outV, int M)
{
    extern __shared__ uint32_t sm[];
    uint32_t* Ah = sm;
    uint32_t* Al = sm + AREA;
    float* bshk = (float*)(sm + 2 * AREA);
    float* bshv = bshk + 128;

    const int t = threadIdx.x;
    if (t < 128) bshk[t] = bk[t];
    else         bshv[t - 128] = bv[t - 128];

    const int w = t >> 5, lane = t & 31, g = lane >> 2, tig = lane & 3;
    const int ntiles = (M + 127) >> 7;

    for (int tile = blockIdx.x; tile < ntiles; tile += gridDim.x) {
        const int m0 = tile << 7;
        __syncthreads();
        convert_tile(A, m0, M, Ah, Al, (const float*)0);
        __syncthreads();

        float acc[64];
        #pragma unroll
        for (int i = 0; i < 64; i++) acc[i] = 0.0f;
        tile_compute(Ah, Al, Wkh, Wkl, acc, w, g, tig);
        epilogue_write(acc, bshk, outK, m0, M, w, g, tig);

        #pragma unroll
        for (int i = 0; i < 64; i++) acc[i] = 0.0f;
        tile_compute(Ah, Al, Wvh, Wvl, acc, w, g, tig);
        epilogue_write(acc, bshv, outV, m0, M, w, g, tig);
    }
}

// ---------------- h GEMM: h = deg*(x_mid@W1^T) + smid@W2^T + deg*(b1+b2) ----
__global__ void __launch_bounds__(256, 2) gemmh_mma_kernel(
    const float* __restrict__ x_mid,
    const uint32_t* __restrict__ W1h, const uint32_t* __restrict__ W1l,
    const float* __restrict__ b1,
    const uint32_t* __restrict__ W2h, const uint32_t* __restrict__ W2l,
    const float* __restrict__ b2)
{
    extern __shared__ uint32_t sm[];
    uint32_t* Ah = sm;
    uint32_t* Al = sm + AREA;
    float* bsh = (float*)(sm + 2 * AREA);

    const int t = threadIdx.x;
    if (t < 128) bsh[t] = b1[t] + b2[t];

    const int w = t >> 5, lane = t & 31, g = lane >> 2, tig = lane & 3;
    const int ntiles = (NM + 127) >> 7;

    for (int tile = blockIdx.x; tile < ntiles; tile += gridDim.x) {
        const int m0 = tile << 7;
        float acc[64];
        #pragma unroll
        for (int i = 0; i < 64; i++) acc[i] = 0.0f;

        __syncthreads();
        convert_tile(x_mid, m0, NM, Ah, Al, g_deg);   // rows scaled by deg
        __syncthreads();
        tile_compute(Ah, Al, W1h, W1l, acc, w, g, tig);

        __syncthreads();
        convert_tile(g_smid, m0, NM, Ah, Al, (const float*)0);
        __syncthreads();
        tile_compute(Ah, Al, W2h, W2l, acc, w, g, tig);

        const int r0 = m0 + w * 16 + g;
        const int r1 = r0 + 8;
        const float d0 = (r0 < NM) ? g_deg[r0] : 0.0f;
        const float d1 = (r1 < NM) ? g_deg[r1] : 0.0f;
        #pragma unroll
        for (int nt = 0; nt < 16; nt++) {
            const int c = nt * 8 + tig * 2;
            const float b0 = bsh[c], b1v = bsh[c + 1];
            if (r0 < NM) {
                float2 o = { acc[nt*4+0] + d0 * b0, acc[nt*4+1] + d0 * b1v };
                *(float2*)(g_h + (size_t)r0 * C + c) = o;
            }
            if (r1 < NM) {
                float2 o = { acc[nt*4+2] + d1 * b0, acc[nt*4+3] + d1 * b1v };
                *(float2*)(g_h + (size_t)r1 * C + c) = o;
            }
        }
    }
}

// ---------------- zeroing (vectorized, one kernel) ---------------------------
__global__ void __launch_bounds__(256) zero_all_kernel(float4* out4) {
    const long long i  = (long long)blockIdx.x * blockDim.x + threadIdx.x;
    const long long st = (long long)gridDim.x * blockDim.x;
    const float4 z = make_float4(0.f, 0.f, 0.f, 0.f);
    float4* s4 = (float4*)g_smid;
    const long long n4 = (long long)NM * C / 4;
    for (long long k = i; k < n4; k += st) s4[k] = z;
    float4* d4 = (float4*)g_deg;
    for (long long k = i; k < NM / 4; k += st) d4[k] = z;
    const long long o4 = (long long)ND * C / 4;
    for (long long k = i; k < o4; k += st) out4[k] = z;
    if (i == 0) g_sum[0] = 0.0f;
}
__global__ void detect_kernel(const void* ei) {
    if (blockIdx.x == 0 && threadIdx.x == 0) {
        const unsigned* w = (const unsigned*)ei;
        int all0 = 1;
        for (int k = 0; k < 64; k++)
            if (w[2 * k + 1] != 0u) { all0 = 0; break; }
        g_idx64 = all0;
    }
}

// ---------------- stage-1 scatter (x4 unrolled) ------------------------------
__global__ void __launch_bounds__(256) scatter1_kernel(const void* ei1, const float* x_src) {
    const int is64 = g_idx64;
    const int lane = threadIdx.x & 31;
    const int warp  = (blockIdx.x * blockDim.x + threadIdx.x) >> 5;
    const int nwarp = (gridDim.x * blockDim.x) >> 5;
    const float4* xs4 = (const float4*)x_src;
    int e = warp;
    for (; e + 3 * nwarp < NE1; e += 4 * nwarp) {
        int s[4], m[4];
        #pragma unroll
        for (int j = 0; j < 4; j++) {
            s[j] = ld_idx(ei1, e + j * nwarp, is64);
            m[j] = ld_idx(ei1, (long long)NE1 + e + j * nwarp, is64);
        }
        float4 v[4];
        #pragma unroll
        for (int j = 0; j < 4; j++) v[j] = xs4[(size_t)s[j] * 32 + lane];
        #pragma unroll
        for (int j = 0; j < 4; j++)
            red_add_v4(g_smid + (size_t)m[j] * C + lane * 4, v[j]);
        if (lane == 0) {
            #pragma unroll
            for (int j = 0; j < 4; j++) atomicAdd(&g_deg[m[j]], 1.0f);
        }
    }
    for (; e < NE1; e += nwarp) {
        int src = ld_idx(ei1, e, is64);
        int mid = ld_idx(ei1, (long long)NE1 + e, is64);
        float4 v = xs4[(size_t)src * 32 + lane];
        red_add_v4(g_smid + (size_t)mid * C + lane * 4, v);
        if (lane == 0) atomicAdd(&g_deg[mid], 1.0f);
    }
}

// ---------------- edge scores + exp + global sum (x2 unrolled) ---------------
__global__ void __launch_bounds__(256) score_kernel(const void* ei2) {
    const int is64 = g_idx64;
    const int lane = threadIdx.x & 31;
    const int warp  = (blockIdx.x * blockDim.x + threadIdx.x) >> 5;
    const int nwarp = (gridDim.x * blockDim.x) >> 5;
    const float4* Q4 = (const float4*)g_Q;
    const float4* K4 = (const float4*)g_K;
    float wsum = 0.0f;
    int e = warp;
    for (; e + nwarp < NE2; e += 2 * nwarp) {
        int m0 = ld_idx(ei2, e, is64);
        int m1 = ld_idx(ei2, e + nwarp, is64);
        int d0 = ld_idx(ei2, (long long)NE2 + e, is64);
        int d1 = ld_idx(ei2, (long long)NE2 + e + nwarp, is64);
        float4 q0 = Q4[(size_t)d0 * 32 + lane];
        float4 k0 = K4[(size_t)m0 * 32 + lane];
        float4 q1 = Q4[(size_t)d1 * 32 + lane];
        float4 k1 = K4[(size_t)m1 * 32 + lane];
        float p0 = q0.x*k0.x + q0.y*k0.y + q0.z*k0.z + q0.w*k0.w;
        float p1 = q1.x*k1.x + q1.y*k1.y + q1.z*k1.z + q1.w*k1.w;
        #pragma unroll
        for (int off = 16; off; off >>= 1) {
            p0 += __shfl_xor_sync(0xffffffffu, p0, off);
            p1 += __shfl_xor_sync(0xffffffffu, p1, off);
        }
        float e0 = expf(p0 * INV_SQRT_C);
        float e1 = expf(p1 * INV_SQRT_C);
        if (lane == 0) { g_esc[e] = e0; g_esc[e + nwarp] = e1; wsum += e0 + e1; }
    }
    for (; e < NE2; e += nwarp) {
        int mid = ld_idx(ei2, e, is64);
        int dst = ld_idx(ei2, (long long)NE2 + e, is64);
        float4 q = Q4[(size_t)dst * 32 + lane];
        float4 k = K4[(size_t)mid * 32 + lane];
        float p = q.x*k.x + q.y*k.y + q.z*k.z + q.w*k.w;
        #pragma unroll
        for (int off = 16; off; off >>= 1)
            p += __shfl_xor_sync(0xffffffffu, p, off);
        float ev = expf(p * INV_SQRT_C);
        if (lane == 0) { g_esc[e] = ev; wsum += ev; }
    }
    if (lane == 0) atomicAdd(&g_sum[0], wsum);
}

// ---------------- final scatter (x4 unrolled; inv inlined) -------------------
__global__ void __launch_bounds__(256) scatter2_kernel(const void* ei2, float* out) {
    const int is64 = g_idx64;
    const float inv = 1.0f / g_sum[0];
    const int lane = threadIdx.x & 31;
    const int warp  = (blockIdx.x * blockDim.x + threadIdx.x) >> 5;
    const int nwarp = (gridDim.x * blockDim.x) >> 5;
    const float4* V4 = (const float4*)g_V;
    int e = warp;
    for (; e + 3 * nwarp < NE2; e += 4 * nwarp) {
        int m[4], d[4];
        float a[4];
        #pragma unroll
        for (int j = 0; j < 4; j++) {
            m[j] = ld_idx(ei2, e + j * nwarp, is64);
            d[j] = ld_idx(ei2, (long long)NE2 + e + j * nwarp, is64);
            a[j] = g_esc[e + j * nwarp] * inv;
        }
        float4 v[4];
        #pragma unroll
        for (int j = 0; j < 4; j++) v[j] = V4[(size_t)m[j] * 32 + lane];
        #pragma unroll
        for (int j = 0; j < 4; j++) {
            v[j].x *= a[j]; v[j].y *= a[j]; v[j].z *= a[j]; v[j].w *= a[j];
            red_add_v4(out + (size_t)d[j] * C + lane * 4, v[j]);
        }
    }
    for (; e < NE2; e += nwarp) {
        int mid = ld_idx(ei2, e, is64);
        int dst = ld_idx(ei2, (long long)NE2 + e, is64);
        float alpha = g_esc[e] * inv;
        float4 v = V4[(size_t)mid * 32 + lane];
        v.x *= alpha; v.y *= alpha; v.z *= alpha; v.w *= alpha;
        red_add_v4(out + (size_t)dst * C + lane * 4, v);
    }
}

// ---------------------------------------------------------------------------
extern "C" void kernel_launch(void* const* d_in, const int* in_sizes, int n_in,
                              void* d_out, int out_size) {
    const float* x_src = (const float*)d_in[0];
    const float* x_mid = (const float*)d_in[1];
    const float* x_dst = (const float*)d_in[2];
    const void*  ei1   = d_in[3];
    const void*  ei2   = d_in[4];
    const float* W1w   = (const float*)d_in[5];
    const float* W1b   = (const float*)d_in[6];
    const float* W2w   = (const float*)d_in[7];
    const float* W2b   = (const float*)d_in[8];
    const float* qw    = (const float*)d_in[9];
    const float* qb    = (const float*)d_in[10];
    const float* kw    = (const float*)d_in[11];
    const float* kb    = (const float*)d_in[12];
    const float* vw    = (const float*)d_in[13];
    const float* vb    = (const float*)d_in[14];
    float* out = (float*)d_out;

    float *p_h, *p_K, *p_V, *p_Q;
    uint32_t *p_wh, *p_wl;
    cudaGetSymbolAddress((void**)&p_h, g_h);
    cudaGetSymbolAddress((void**)&p_K, g_K);
    cudaGetSymbolAddress((void**)&p_V, g_V);
    cudaGetSymbolAddress((void**)&p_Q, g_Q);
    cudaGetSymbolAddress((void**)&p_wh, g_wh);
    cudaGetSymbolAddress((void**)&p_wl, g_wl);

    cudaFuncSetAttribute(gemm_mma_kernel,
                         cudaFuncAttributeMaxDynamicSharedMemorySize, SMA_BYTES);
    cudaFuncSetAttribute(gemmh_mma_kernel,
                         cudaFuncAttributeMaxDynamicSharedMemorySize, SMA_BYTES);
    cudaFuncSetAttribute(gemm_kv_kernel,
                         cudaFuncAttributeMaxDynamicSharedMemorySize, SMA_BYTES);

    zero_all_kernel<<<1024, 256>>>((float4*)out);
    detect_kernel<<<1, 1>>>(ei1);
    prep_w_kernel<<<dim3(8, 5), 256>>>(W1w, W2w, kw, vw, qw);

    // stage 1: scatter raw features + degrees, then dense h GEMM (HMMA)
    scatter1_kernel<<<1184, 256>>>(ei1, x_src);
    gemmh_mma_kernel<<<296, 256, SMA_BYTES>>>(
        x_mid, p_wh + 0 * WMAT, p_wl + 0 * WMAT, W1b,
               p_wh + 1 * WMAT, p_wl + 1 * WMAT, W2b);

    // stage 2: fused K+V GEMM on h; Q GEMM on x_dst (HMMA)
    gemm_kv_kernel<<<296, 256, SMA_BYTES>>>(
        p_h, p_wh + 2 * WMAT, p_wl + 2 * WMAT, kb, p_K,
             p_wh + 3 * WMAT, p_wl + 3 * WMAT, vb, p_V, NM);
    gemm_mma_kernel<<<296, 256, SMA_BYTES>>>(
        x_dst, p_wh + 4 * WMAT, p_wl + 4 * WMAT, qb, p_Q, ND);

    // edge scores -> global softmax -> weighted scatter
    score_kernel<<<1184, 256>>>(ei2);
    scatter2_kernel<<<1184, 256>>>(ei2, out);
}

// round 7
// speedup vs baseline: 1.4931x; 1.4931x over previous
#include <cuda_runtime.h>
#include <cuda_bf16.h>
#include <cstdint>
#include <math.h>

// ---------------------------------------------------------------------------
// AtomicRouteConv — restructured GNN pipeline.
// GEMMs on HMMA (mma.sync m16n8k16 bf16) with split-bf16 fp32 emulation:
//   A = Ah + Al, B = Bh + Bl;  D = Ah*Bh + Ah*Bl + Al*Bh  (err ~1.5e-5)
// R7: revert weights to smem (R6 LDG-in-loop regressed); 512-thread CTAs,
//     warp-pairs split N -> 16 warps hide LDS/MMA latency; unified GEMM
//     kernel with rowscale/biasdeg/accumulate flags (gemmh = 2 passes).
// ---------------------------------------------------------------------------

#define C      128
#define NM     50000
#define ND     50000
#define NE1    640000
#define NE2    640000
#define INV_SQRT_C 0.08838834764831843f

// padded smem row: 128 bf16 = 64 words, pad to 68 words (conflict-free frag reads)
#define RP 68
#define RP8 (8*RP)
#define AREA (128*RP)            // words per hi or lo region (34816 B)

// ---------------- scratch ----------------------------------------------------
__device__ __align__(16) float g_smid[NM * C];
__device__ __align__(16) float g_deg [NM + 48];
__device__ __align__(16) float g_h   [NM * C];
__device__ __align__(16) float g_K   [NM * C];
__device__ __align__(16) float g_V   [NM * C];
__device__ __align__(16) float g_Q   [ND * C];
__device__ __align__(16) float g_esc [NE2];
__device__ float g_sum[1];
__device__ int   g_idx64;

// ---------------- helpers ---------------------------------------------------
__device__ __forceinline__ int ld_idx(const void* ei, long long pos, int is64) {
    if (is64) return (int)(((const long long*)ei)[pos]);
    return ((const int*)ei)[pos];
}
__device__ __forceinline__ void red_add_v4(float* p, float4 v) {
    asm volatile("red.global.add.v4.f32 [%0], {%1,%2,%3,%4};"
                 :: "l"(p), "f"(v.x), "f"(v.y), "f"(v.z), "f"(v.w) : "memory");
}
// split two fp32 into packed bf16x2 hi + lo (lo-half = f0, hi-half = f1)
__device__ __forceinline__ void split2(float f0, float f1, uint32_t& h, uint32_t& l) {
    uint32_t hp;
    asm("cvt.rn.bf16x2.f32 %0, %1, %2;" : "=r"(hp) : "f"(f1), "f"(f0));
    float f0h = __uint_as_float(hp << 16);
    float f1h = __uint_as_float(hp & 0xffff0000u);
    float r0 = f0 - f0h, r1 = f1 - f1h;
    asm("cvt.rn.bf16x2.f32 %0, %1, %2;" : "=r"(l) : "f"(r1), "f"(r0));
    h = hp;
}
__device__ __forceinline__ void mma_bf16(float* c, const uint32_t* a,
                                         uint32_t b0, uint32_t b1) {
    asm volatile("mma.sync.aligned.m16n8k16.row.col.f32.bf16.bf16.f32 "
        "{%0,%1,%2,%3}, {%4,%5,%6,%7}, {%8,%9}, {%0,%1,%2,%3};"
        : "+f"(c[0]), "+f"(c[1]), "+f"(c[2]), "+f"(c[3])
        : "r"(a[0]), "r"(a[1]), "r"(a[2]), "r"(a[3]), "r"(b0), "r"(b1));
}

// convert a 128x128 fp32 tile into hi/lo bf16 smem, optional per-row scale.
// 512 threads: thread t -> row t>>2, col quarter (t&3)*32.
__device__ __forceinline__ void convert_tile512(const float* __restrict__ A, int m0, int M,
                                                uint32_t* __restrict__ Dh,
                                                uint32_t* __restrict__ Dl,
                                                const float* __restrict__ rowscale) {
    const int t = threadIdx.x;
    const int r = t >> 2, q = t & 3;
    const int row = m0 + r;
    const bool v = row < M;
    const float s = (rowscale && v) ? rowscale[row] : 1.0f;
    const float4* Ar = (const float4*)(A + (size_t)row * C + q * 32);
    const int wb = r * RP + q * 16;
    #pragma unroll
    for (int i = 0; i < 8; i++) {
        float4 x = v ? Ar[i] : make_float4(0.f, 0.f, 0.f, 0.f);
        uint32_t h0, l0, h1, l1;
        split2(s * x.x, s * x.y, h0, l0);
        split2(s * x.z, s * x.w, h1, l1);
        Dh[wb + i*2]   = h0; Dh[wb + i*2+1] = h1;
        Dl[wb + i*2]   = l0; Dl[wb + i*2+1] = l1;
    }
}

// convert a weight matrix [128][128] into hi/lo smem regions (512 threads)
__device__ __forceinline__ void convert_w512(const float* __restrict__ W,
                                             uint32_t* __restrict__ Wh,
                                             uint32_t* __restrict__ Wl) {
    const int t = threadIdx.x;
    const int r = t >> 2, q = t & 3;
    const float4* Wr = (const float4*)(W + r * C + q * 32);
    const int wb = r * RP + q * 16;
    #pragma unroll
    for (int i = 0; i < 8; i++) {
        float4 x = Wr[i];
        uint32_t h0, l0, h1, l1;
        split2(x.x, x.y, h0, l0);
        split2(x.z, x.w, h1, l1);
        Wh[wb + i*2]   = h0; Wh[wb + i*2+1] = h1;
        Wl[wb + i*2]   = l0; Wl[wb + i*2+1] = l1;
    }
}

#define SMU_BYTES (4 * AREA * 4 + 512)

// ---------------- unified GEMM: out[M,128] = (rs.*A)[M,128] @ W^T (+bias)(+=)
// 512 threads, 16 warps. Warp pair wp=w>>1 covers rows wp*16..wp*16+15;
// parity par=w&1 covers n-tiles par*8..par*8+7 (acc[32] per thread).
__global__ void __launch_bounds__(512) gemm_uni_kernel(
    const float* __restrict__ A, const float* __restrict__ W,
    const float* __restrict__ bias1, const float* __restrict__ bias2,
    float* __restrict__ out, int M,
    const float* __restrict__ rowscale, int biasdeg, int accum)
{
    extern __shared__ uint32_t sm[];
    uint32_t* Ah = sm;
    uint32_t* Al = sm + AREA;
    uint32_t* Wh = sm + 2 * AREA;
    uint32_t* Wl = sm + 3 * AREA;
    float* bsh = (float*)(sm + 4 * AREA);

    const int t = threadIdx.x;
    convert_w512(W, Wh, Wl);
    if (t < 128) bsh[t] = (bias1 ? bias1[t] : 0.0f) + (bias2 ? bias2[t] : 0.0f);

    const int w = t >> 5, lane = t & 31;
    const int wp = w >> 1, par = w & 1;
    const int g = lane >> 2, tig = lane & 3;
    const int ntiles = (M + 127) >> 7;

    for (int tile = blockIdx.x; tile < ntiles; tile += gridDim.x) {
        const int m0 = tile << 7;
        __syncthreads();
        convert_tile512(A, m0, M, Ah, Al, rowscale);
        __syncthreads();

        float acc[32];
        #pragma unroll
        for (int i = 0; i < 32; i++) acc[i] = 0.0f;

        #pragma unroll 1
        for (int ks = 0; ks < 8; ks++) {
            uint32_t ah[4], al[4];
            const int ab = (wp * 16 + g) * RP + ks * 8 + tig;
            ah[0] = Ah[ab];     ah[1] = Ah[ab + RP8];
            ah[2] = Ah[ab + 4]; ah[3] = Ah[ab + RP8 + 4];
            al[0] = Al[ab];     al[1] = Al[ab + RP8];
            al[2] = Al[ab + 4]; al[3] = Al[ab + RP8 + 4];
            #pragma unroll
            for (int nt = 0; nt < 8; nt++) {
                const int nb = ((par * 8 + nt) * 8 + g) * RP + ks * 8 + tig;
                uint32_t bh0 = Wh[nb], bh1 = Wh[nb + 4];
                uint32_t bl0 = Wl[nb], bl1 = Wl[nb + 4];
                float* cc = acc + nt * 4;
                mma_bf16(cc, ah, bh0, bh1);
                mma_bf16(cc, ah, bl0, bl1);
                mma_bf16(cc, al, bh0, bh1);
            }
        }

        const int r0 = m0 + wp * 16 + g;
        const int r1 = r0 + 8;
        float d0 = 1.0f, d1 = 1.0f;
        if (biasdeg) {
            d0 = (r0 < M) ? g_deg[r0] : 0.0f;
            d1 = (r1 < M) ? g_deg[r1] : 0.0f;
        }
        #pragma unroll
        for (int nt = 0; nt < 8; nt++) {
            const int c = (par * 8 + nt) * 8 + tig * 2;
            const float b0 = bsh[c], b1v = bsh[c + 1];
            if (r0 < M) {
                float ox = acc[nt*4+0] + d0 * b0;
                float oy = acc[nt*4+1] + d0 * b1v;
                float* p = out + (size_t)r0 * C + c;
                if (accum) { float2 pv = *(float2*)p; ox += pv.x; oy += pv.y; }
                float2 o = { ox, oy };
                *(float2*)p = o;
            }
            if (r1 < M) {
                float ox = acc[nt*4+2] + d1 * b0;
                float oy = acc[nt*4+3] + d1 * b1v;
                float* p = out + (size_t)r1 * C + c;
                if (accum) { float2 pv = *(float2*)p; ox += pv.x; oy += pv.y; }
                float2 o = { ox, oy };
                *(float2*)p = o;
            }
        }
    }
}

// ---------------- zeroing (vectorized, one kernel) ---------------------------
__global__ void __launch_bounds__(256) zero_all_kernel(float4* out4) {
    const long long i  = (long long)blockIdx.x * blockDim.x + threadIdx.x;
    const long long st = (long long)gridDim.x * blockDim.x;
    const float4 z = make_float4(0.f, 0.f, 0.f, 0.f);
    float4* s4 = (float4*)g_smid;
    const long long n4 = (long long)NM * C / 4;
    for (long long k = i; k < n4; k += st) s4[k] = z;
    float4* d4 = (float4*)g_deg;
    for (long long k = i; k < NM / 4; k += st) d4[k] = z;
    const long long o4 = (long long)ND * C / 4;
    for (long long k = i; k < o4; k += st) out4[k] = z;
    if (i == 0) g_sum[0] = 0.0f;
}
__global__ void detect_kernel(const void* ei) {
    if (blockIdx.x == 0 && threadIdx.x == 0) {
        const unsigned* w = (const unsigned*)ei;
        int all0 = 1;
        for (int k = 0; k < 64; k++)
            if (w[2 * k + 1] != 0u) { all0 = 0; break; }
        g_idx64 = all0;
    }
}

// ---------------- stage-1 scatter (x4 unrolled) ------------------------------
__global__ void __launch_bounds__(256) scatter1_kernel(const void* ei1, const float* x_src) {
    const int is64 = g_idx64;
    const int lane = threadIdx.x & 31;
    const int warp  = (blockIdx.x * blockDim.x + threadIdx.x) >> 5;
    const int nwarp = (gridDim.x * blockDim.x) >> 5;
    const float4* xs4 = (const float4*)x_src;
    int e = warp;
    for (; e + 3 * nwarp < NE1; e += 4 * nwarp) {
        int s[4], m[4];
        #pragma unroll
        for (int j = 0; j < 4; j++) {
            s[j] = ld_idx(ei1, e + j * nwarp, is64);
            m[j] = ld_idx(ei1, (long long)NE1 + e + j * nwarp, is64);
        }
        float4 v[4];
        #pragma unroll
        for (int j = 0; j < 4; j++) v[j] = xs4[(size_t)s[j] * 32 + lane];
        #pragma unroll
        for (int j = 0; j < 4; j++)
            red_add_v4(g_smid + (size_t)m[j] * C + lane * 4, v[j]);
        if (lane == 0) {
            #pragma unroll
            for (int j = 0; j < 4; j++) atomicAdd(&g_deg[m[j]], 1.0f);
        }
    }
    for (; e < NE1; e += nwarp) {
        int src = ld_idx(ei1, e, is64);
        int mid = ld_idx(ei1, (long long)NE1 + e, is64);
        float4 v = xs4[(size_t)src * 32 + lane];
        red_add_v4(g_smid + (size_t)mid * C + lane * 4, v);
        if (lane == 0) atomicAdd(&g_deg[mid], 1.0f);
    }
}

// ---------------- edge scores + exp + global sum (x2 unrolled) ---------------
__global__ void __launch_bounds__(256) score_kernel(const void* ei2) {
    const int is64 = g_idx64;
    const int lane = threadIdx.x & 31;
    const int warp  = (blockIdx.x * blockDim.x + threadIdx.x) >> 5;
    const int nwarp = (gridDim.x * blockDim.x) >> 5;
    const float4* Q4 = (const float4*)g_Q;
    const float4* K4 = (const float4*)g_K;
    float wsum = 0.0f;
    int e = warp;
    for (; e + nwarp < NE2; e += 2 * nwarp) {
        int m0 = ld_idx(ei2, e, is64);
        int m1 = ld_idx(ei2, e + nwarp, is64);
        int d0 = ld_idx(ei2, (long long)NE2 + e, is64);
        int d1 = ld_idx(ei2, (long long)NE2 + e + nwarp, is64);
        float4 q0 = Q4[(size_t)d0 * 32 + lane];
        float4 k0 = K4[(size_t)m0 * 32 + lane];
        float4 q1 = Q4[(size_t)d1 * 32 + lane];
        float4 k1 = K4[(size_t)m1 * 32 + lane];
        float p0 = q0.x*k0.x + q0.y*k0.y + q0.z*k0.z + q0.w*k0.w;
        float p1 = q1.x*k1.x + q1.y*k1.y + q1.z*k1.z + q1.w*k1.w;
        #pragma unroll
        for (int off = 16; off; off >>= 1) {
            p0 += __shfl_xor_sync(0xffffffffu, p0, off);
            p1 += __shfl_xor_sync(0xffffffffu, p1, off);
        }
        float e0 = expf(p0 * INV_SQRT_C);
        float e1 = expf(p1 * INV_SQRT_C);
        if (lane == 0) { g_esc[e] = e0; g_esc[e + nwarp] = e1; wsum += e0 + e1; }
    }
    for (; e < NE2; e += nwarp) {
        int mid = ld_idx(ei2, e, is64);
        int dst = ld_idx(ei2, (long long)NE2 + e, is64);
        float4 q = Q4[(size_t)dst * 32 + lane];
        float4 k = K4[(size_t)mid * 32 + lane];
        float p = q.x*k.x + q.y*k.y + q.z*k.z + q.w*k.w;
        #pragma unroll
        for (int off = 16; off; off >>= 1)
            p += __shfl_xor_sync(0xffffffffu, p, off);
        float ev = expf(p * INV_SQRT_C);
        if (lane == 0) { g_esc[e] = ev; wsum += ev; }
    }
    if (lane == 0) atomicAdd(&g_sum[0], wsum);
}

// ---------------- final scatter (x4 unrolled; inv inlined) -------------------
__global__ void __launch_bounds__(256) scatter2_kernel(const void* ei2, float* out) {
    const int is64 = g_idx64;
    const float inv = 1.0f / g_sum[0];
    const int lane = threadIdx.x & 31;
    const int warp  = (blockIdx.x * blockDim.x + threadIdx.x) >> 5;
    const int nwarp = (gridDim.x * blockDim.x) >> 5;
    const float4* V4 = (const float4*)g_V;
    int e = warp;
    for (; e + 3 * nwarp < NE2; e += 4 * nwarp) {
        int m[4], d[4];
        float a[4];
        #pragma unroll
        for (int j = 0; j < 4; j++) {
            m[j] = ld_idx(ei2, e + j * nwarp, is64);
            d[j] = ld_idx(ei2, (long long)NE2 + e + j * nwarp, is64);
            a[j] = g_esc[e + j * nwarp] * inv;
        }
        float4 v[4];
        #pragma unroll
        for (int j = 0; j < 4; j++) v[j] = V4[(size_t)m[j] * 32 + lane];
        #pragma unroll
        for (int j = 0; j < 4; j++) {
            v[j].x *= a[j]; v[j].y *= a[j]; v[j].z *= a[j]; v[j].w *= a[j];
            red_add_v4(out + (size_t)d[j] * C + lane * 4, v[j]);
        }
    }
    for (; e < NE2; e += nwarp) {
        int mid = ld_idx(ei2, e, is64);
        int dst = ld_idx(ei2, (long long)NE2 + e, is64);
        float alpha = g_esc[e] * inv;
        float4 v = V4[(size_t)mid * 32 + lane];
        v.x *= alpha; v.y *= alpha; v.z *= alpha; v.w *= alpha;
        red_add_v4(out + (size_t)dst * C + lane * 4, v);
    }
}

// ---------------------------------------------------------------------------
extern "C" void kernel_launch(void* const* d_in, const int* in_sizes, int n_in,
                              void* d_out, int out_size) {
    const float* x_src = (const float*)d_in[0];
    const float* x_mid = (const float*)d_in[1];
    const float* x_dst = (const float*)d_in[2];
    const void*  ei1   = d_in[3];
    const void*  ei2   = d_in[4];
    const float* W1w   = (const float*)d_in[5];
    const float* W1b   = (const float*)d_in[6];
    const float* W2w   = (const float*)d_in[7];
    const float* W2b   = (const float*)d_in[8];
    const float* qw    = (const float*)d_in[9];
    const float* qb    = (const float*)d_in[10];
    const float* kw    = (const float*)d_in[11];
    const float* kb    = (const float*)d_in[12];
    const float* vw    = (const float*)d_in[13];
    const float* vb    = (const float*)d_in[14];
    float* out = (float*)d_out;

    float *p_h, *p_K, *p_V, *p_Q, *p_smid, *p_deg;
    cudaGetSymbolAddress((void**)&p_h, g_h);
    cudaGetSymbolAddress((void**)&p_K, g_K);
    cudaGetSymbolAddress((void**)&p_V, g_V);
    cudaGetSymbolAddress((void**)&p_Q, g_Q);
    cudaGetSymbolAddress((void**)&p_smid, g_smid);
    cudaGetSymbolAddress((void**)&p_deg, g_deg);

    cudaFuncSetAttribute(gemm_uni_kernel,
                         cudaFuncAttributeMaxDynamicSharedMemorySize, SMU_BYTES);

    zero_all_kernel<<<1024, 256>>>((float4*)out);
    detect_kernel<<<1, 1>>>(ei1);

    // stage 1: scatter raw features + degrees
    scatter1_kernel<<<1184, 256>>>(ei1, x_src);

    // h = (deg.*x_mid)@W1^T + deg*(b1+b2)  ;  h += smid@W2^T
    gemm_uni_kernel<<<148, 512, SMU_BYTES>>>(x_mid, W1w, W1b, W2b, p_h, NM,
                                             p_deg, 1, 0);
    gemm_uni_kernel<<<148, 512, SMU_BYTES>>>(p_smid, W2w, (const float*)0,
                                             (const float*)0, p_h, NM,
                                             (const float*)0, 0, 1);

    // K, V on h; Q on x_dst
    gemm_uni_kernel<<<148, 512, SMU_BYTES>>>(p_h, kw, kb, (const float*)0, p_K, NM,
                                             (const float*)0, 0, 0);
    gemm_uni_kernel<<<148, 512, SMU_BYTES>>>(p_h, vw, vb, (const float*)0, p_V, NM,
                                             (const float*)0, 0, 0);
    gemm_uni_kernel<<<148, 512, SMU_BYTES>>>(x_dst, qw, qb, (const float*)0, p_Q, ND,
                                             (const float*)0, 0, 0);

    // edge scores -> global softmax -> weighted scatter
    score_kernel<<<1184, 256>>>(ei2);
    scatter2_kernel<<<1184, 256>>>(ei2, out);
}